// round 1
// baseline (speedup 1.0000x reference)
#include <cuda_runtime.h>
#include <cstdint>

// Problem constants
#define NS      16
#define N_ATOMS 2000
#define NB      2000
#define NA      4000
#define NVV     400000
#define NT      6000
#define NI      1000

// Output row layout (per sample), total 819001 floats
#define OFF_EBOND   0
#define OFF_EANGLE  2000
#define OFF_EUB     6000
#define OFF_EVDW    6001
#define OFF_ECHG    406001
#define OFF_ETOR    806001
#define OFF_EIMP    812001
#define OFF_FORCE   813001
#define ROW         819001

#define K2C_HALF 1.8222615f   // CHARGE/10

// ---------------------------------------------------------------------------
// Zero the Force region and E_ub
// ---------------------------------------------------------------------------
__global__ void zero_kernel(float* __restrict__ out) {
    int idx = blockIdx.x * blockDim.x + threadIdx.x;
    const int total = NS * (3 * N_ATOMS + 1);
    if (idx >= total) return;
    int s = idx / (3 * N_ATOMS + 1);
    int k = idx % (3 * N_ATOMS + 1);
    size_t base = (size_t)s * ROW;
    if (k < 3 * N_ATOMS)
        out[base + OFF_FORCE + k] = 0.0f;
    else
        out[base + OFF_EUB] = 0.0f;
}

// ---------------------------------------------------------------------------
// Bond term
// ---------------------------------------------------------------------------
__global__ void bond_kernel(const float* __restrict__ length_bond,
                            const float* __restrict__ paras_bond,
                            const float* __restrict__ dlength_bond,
                            const int*   __restrict__ bond_index,
                            float* __restrict__ out) {
    int b = blockIdx.x * blockDim.x + threadIdx.x;
    if (b >= NB) return;
    int s = blockIdx.y;
    float2 pb = ((const float2*)paras_bond)[b];
    float K  = pb.x * 100.0f;
    float d  = length_bond[(size_t)s * NB + b] - pb.y;
    size_t base = (size_t)s * ROW;
    out[base + OFF_EBOND + b] = K * d * d;
    float Fs = 2.0f * K * d;
    const float2* D = (const float2*)(dlength_bond + ((size_t)s * NB + b) * 6);
    float2 d0 = D[0], d1 = D[1], d2 = D[2];
    int2 ab = ((const int2*)bond_index)[b];
    float* F = out + base + OFF_FORCE;
    atomicAdd(&F[ab.x * 3 + 0], d0.x * Fs);
    atomicAdd(&F[ab.x * 3 + 1], d0.y * Fs);
    atomicAdd(&F[ab.x * 3 + 2], d1.x * Fs);
    atomicAdd(&F[ab.y * 3 + 0], d1.y * Fs);
    atomicAdd(&F[ab.y * 3 + 1], d2.x * Fs);
    atomicAdd(&F[ab.y * 3 + 2], d2.y * Fs);
}

// ---------------------------------------------------------------------------
// Angle term
// ---------------------------------------------------------------------------
__global__ void angle_kernel(const float* __restrict__ theta_angle,
                             const float* __restrict__ paras_angle,
                             const float* __restrict__ dtheta_angle,
                             const int*   __restrict__ angle_index,
                             float* __restrict__ out) {
    int a = blockIdx.x * blockDim.x + threadIdx.x;
    if (a >= NA) return;
    int s = blockIdx.y;
    float2 pa = ((const float2*)paras_angle)[a];
    float Ka  = pa.x * 10.0f;
    float th0 = pa.y * 0.3141592653589793f;
    float da  = theta_angle[(size_t)s * NA + a] - th0;
    size_t base = (size_t)s * ROW;
    out[base + OFF_EANGLE + a] = Ka * da * da;
    float Fs = 2.0f * Ka * da;
    const float* D = dtheta_angle + ((size_t)s * NA + a) * 9;
    float* F = out + base + OFF_FORCE;
    #pragma unroll
    for (int k = 0; k < 3; k++) {
        int atom = angle_index[a * 3 + k];
        #pragma unroll
        for (int c = 0; c < 3; c++)
            atomicAdd(&F[atom * 3 + c], D[k * 3 + c] * Fs);
    }
}

// ---------------------------------------------------------------------------
// Torsion term
// ---------------------------------------------------------------------------
__global__ void torsion_kernel(const float* __restrict__ sin_cos_torsion,
                               const float* __restrict__ paras_torsion,
                               const float* __restrict__ dtheta_torsion,
                               const int*   __restrict__ torsion_index,
                               float* __restrict__ out) {
    int t = blockIdx.x * blockDim.x + threadIdx.x;
    if (t >= NT) return;
    int s = blockIdx.y;
    const float4* SC = (const float4*)(sin_cos_torsion + ((size_t)s * NT + t) * 8);
    float4 sc0 = SC[0];   // sin1, cos1, sin2, cos2
    float4 sc1 = SC[1];   // sin3, cos3, sin4, cos4
    float4 p = ((const float4*)paras_torsion)[t];
    size_t base = (size_t)s * ROW;
    float E = sc0.y * p.x + sc0.w * p.y + sc1.y * p.z + sc1.w * p.w;
    out[base + OFF_ETOR + t] = E;
    float Fs = -(sc0.x * p.x + sc0.z * (2.0f * p.y) + sc1.x * (3.0f * p.z) + sc1.z * (4.0f * p.w));
    const float4* D = (const float4*)(dtheta_torsion + ((size_t)s * NT + t) * 12);
    float4 dA = D[0], dB = D[1], dC = D[2];
    int4 ti = ((const int4*)torsion_index)[t];
    float* F = out + base + OFF_FORCE;
    atomicAdd(&F[ti.x * 3 + 0], dA.x * Fs);
    atomicAdd(&F[ti.x * 3 + 1], dA.y * Fs);
    atomicAdd(&F[ti.x * 3 + 2], dA.z * Fs);
    atomicAdd(&F[ti.y * 3 + 0], dA.w * Fs);
    atomicAdd(&F[ti.y * 3 + 1], dB.x * Fs);
    atomicAdd(&F[ti.y * 3 + 2], dB.y * Fs);
    atomicAdd(&F[ti.z * 3 + 0], dB.z * Fs);
    atomicAdd(&F[ti.z * 3 + 1], dB.w * Fs);
    atomicAdd(&F[ti.z * 3 + 2], dC.x * Fs);
    atomicAdd(&F[ti.w * 3 + 0], dC.y * Fs);
    atomicAdd(&F[ti.w * 3 + 1], dC.z * Fs);
    atomicAdd(&F[ti.w * 3 + 2], dC.w * Fs);
}

// ---------------------------------------------------------------------------
// Imptors term
// ---------------------------------------------------------------------------
__global__ void imptors_kernel(const float* __restrict__ cos2_imptors,
                               const float* __restrict__ paras_imptors,
                               const float* __restrict__ dcos2_imptors,
                               const int*   __restrict__ imptors_index,
                               float* __restrict__ out) {
    int i = blockIdx.x * blockDim.x + threadIdx.x;
    if (i >= NI) return;
    int s = blockIdx.y;
    float ki = paras_imptors[i];
    size_t base = (size_t)s * ROW;
    out[base + OFF_EIMP + i] = ki * (1.0f - cos2_imptors[(size_t)s * NI + i]);
    float Fs = -ki;
    const float4* D = (const float4*)(dcos2_imptors + ((size_t)s * NI + i) * 12);
    float4 dA = D[0], dB = D[1], dC = D[2];
    int4 ii = ((const int4*)imptors_index)[i];
    float* F = out + base + OFF_FORCE;
    atomicAdd(&F[ii.x * 3 + 0], dA.x * Fs);
    atomicAdd(&F[ii.x * 3 + 1], dA.y * Fs);
    atomicAdd(&F[ii.x * 3 + 2], dA.z * Fs);
    atomicAdd(&F[ii.y * 3 + 0], dA.w * Fs);
    atomicAdd(&F[ii.y * 3 + 1], dB.x * Fs);
    atomicAdd(&F[ii.y * 3 + 2], dB.y * Fs);
    atomicAdd(&F[ii.z * 3 + 0], dB.z * Fs);
    atomicAdd(&F[ii.z * 3 + 1], dB.w * Fs);
    atomicAdd(&F[ii.z * 3 + 2], dC.x * Fs);
    atomicAdd(&F[ii.w * 3 + 0], dC.y * Fs);
    atomicAdd(&F[ii.w * 3 + 1], dC.z * Fs);
    atomicAdd(&F[ii.w * 3 + 2], dC.w * Fs);
}

// ---------------------------------------------------------------------------
// Fused vdW + charge term (the heavy one).
// One block = (pair chunk, sample). Shared-memory privatized force (24 KB),
// flushed with one global RED per slot.
// ---------------------------------------------------------------------------
#define VDW_CHUNK   16000     // 25 chunks cover NVV
#define VDW_THREADS 256

__global__ __launch_bounds__(VDW_THREADS)
void vdw_kernel(const float* __restrict__ length_vdw,
                const float* __restrict__ dlength_vdw,
                const float* __restrict__ vdw14,
                const float* __restrict__ charge14,
                const float2* __restrict__ paras_vdw,
                const float* __restrict__ paras_charge,
                const int*   __restrict__ nonbonded,
                const int2*  __restrict__ nbindex,
                float* __restrict__ out) {
    __shared__ float sF[3 * N_ATOMS];
    const int s  = blockIdx.y;
    const int c0 = blockIdx.x * VDW_CHUNK;

    for (int k = threadIdx.x; k < 3 * N_ATOMS; k += VDW_THREADS) sF[k] = 0.0f;
    __syncthreads();

    const float* Lrow = length_vdw + (size_t)s * NVV;
    const float* Drow = dlength_vdw + (size_t)s * NVV * 6;
    size_t base = (size_t)s * ROW;
    float* Ev = out + base + OFF_EVDW;
    float* Ec = out + base + OFF_ECHG;

    for (int p = c0 + threadIdx.x; p < c0 + VDW_CHUNK; p += VDW_THREADS) {
        int i = nonbonded[p];
        int j = nonbonded[NVV + p];
        float2 pvi = paras_vdw[i];
        float2 pvj = paras_vdw[j];
        float sigma = pvi.x + pvj.x;
        float eps   = (pvi.y * 0.1f) * (pvj.y * 0.1f) * vdw14[p];
        float cc    = (K2C_HALF * paras_charge[i]) * (K2C_HALF * paras_charge[j]) * charge14[p];

        float r   = Lrow[p];
        float ir  = __fdividef(1.0f, r);
        float ir2 = ir * ir;
        float s2  = sigma * sigma;
        float t   = (s2 * s2 * s2) * (ir2 * ir2 * ir2);

        Ev[p] = eps * (t * t - 2.0f * t);
        Ec[p] = cc * ir;

        float w = 12.0f * eps * t * (1.0f - t) * ir - cc * ir2;

        const float2* D = (const float2*)(Drow + (size_t)p * 6);
        float2 d0 = D[0], d1 = D[1], d2 = D[2];
        int2 ab = nbindex[p];
        atomicAdd(&sF[ab.x * 3 + 0], d0.x * w);
        atomicAdd(&sF[ab.x * 3 + 1], d0.y * w);
        atomicAdd(&sF[ab.x * 3 + 2], d1.x * w);
        atomicAdd(&sF[ab.y * 3 + 0], d1.y * w);
        atomicAdd(&sF[ab.y * 3 + 1], d2.x * w);
        atomicAdd(&sF[ab.y * 3 + 2], d2.y * w);
    }
    __syncthreads();

    float* F = out + base + OFF_FORCE;
    for (int k = threadIdx.x; k < 3 * N_ATOMS; k += VDW_THREADS)
        atomicAdd(&F[k], sF[k]);
}

// ---------------------------------------------------------------------------
// Launch
// ---------------------------------------------------------------------------
extern "C" void kernel_launch(void* const* d_in, const int* in_sizes, int n_in,
                              void* d_out, int out_size) {
    const float* length_bond     = (const float*)d_in[0];
    const float* theta_angle     = (const float*)d_in[1];
    const float* length_vdw      = (const float*)d_in[2];
    const float* sin_cos_torsion = (const float*)d_in[3];
    const float* cos2_imptors    = (const float*)d_in[4];
    const float* vdw14           = (const float*)d_in[5];
    const float* charge14        = (const float*)d_in[6];
    const float* paras_bond      = (const float*)d_in[7];
    const float* paras_angle     = (const float*)d_in[8];
    const float* paras_vdw       = (const float*)d_in[9];
    const float* paras_charge    = (const float*)d_in[10];
    const float* paras_torsion   = (const float*)d_in[11];
    const float* paras_imptors   = (const float*)d_in[12];
    const float* dlength_bond    = (const float*)d_in[13];
    const float* dtheta_angle    = (const float*)d_in[14];
    const float* dlength_vdw     = (const float*)d_in[15];
    const float* dtheta_torsion  = (const float*)d_in[16];
    const float* dcos2_imptors   = (const float*)d_in[17];
    const int*   nonbonded       = (const int*)d_in[18];
    const int*   bond_index      = (const int*)d_in[19];
    const int*   angle_index     = (const int*)d_in[20];
    const int*   nonbonded_index = (const int*)d_in[21];
    const int*   torsion_index   = (const int*)d_in[22];
    const int*   imptors_index   = (const int*)d_in[23];
    float* out = (float*)d_out;

    // 1) zero Force region + E_ub
    {
        int total = NS * (3 * N_ATOMS + 1);
        zero_kernel<<<(total + 255) / 256, 256>>>(out);
    }
    // 2) small terms (global RED scatter)
    bond_kernel<<<dim3((NB + 255) / 256, NS), 256>>>(length_bond, paras_bond, dlength_bond, bond_index, out);
    angle_kernel<<<dim3((NA + 255) / 256, NS), 256>>>(theta_angle, paras_angle, dtheta_angle, angle_index, out);
    torsion_kernel<<<dim3((NT + 255) / 256, NS), 256>>>(sin_cos_torsion, paras_torsion, dtheta_torsion, torsion_index, out);
    imptors_kernel<<<dim3((NI + 255) / 256, NS), 256>>>(cos2_imptors, paras_imptors, dcos2_imptors, imptors_index, out);
    // 3) fused vdw + charge (shared-memory privatized scatter)
    vdw_kernel<<<dim3(NVV / VDW_CHUNK, NS), VDW_THREADS>>>(
        length_vdw, dlength_vdw, vdw14, charge14,
        (const float2*)paras_vdw, paras_charge,
        nonbonded, (const int2*)nonbonded_index, out);
}

// round 2
// speedup vs baseline: 1.2708x; 1.2708x over previous
#include <cuda_runtime.h>
#include <cstdint>

// Problem constants
#define NS      16
#define N_ATOMS 2000
#define NB      2000
#define NA      4000
#define NVV     400000
#define NT      6000
#define NI      1000

// Output row layout (per sample), total 819001 floats
#define OFF_EBOND   0
#define OFF_EANGLE  2000
#define OFF_EUB     6000
#define OFF_EVDW    6001
#define OFF_ECHG    406001
#define OFF_ETOR    806001
#define OFF_EIMP    812001
#define OFF_FORCE   813001
#define ROW         819001

#define K2C_HALF 1.8222615f   // CHARGE/10

// Fused kernel decomposition
#define VDW_CHUNKS   25
#define VDW_CHUNK    (NVV / VDW_CHUNKS)     // 16000
#define VDW_BLOCKS   (VDW_CHUNKS * NS)      // 400
#define BONDED_HALVES 2
#define BONDED_BLOCKS (NS * BONDED_HALVES)  // 32
#define TOTAL_BLOCKS (VDW_BLOCKS + BONDED_BLOCKS)
#define NTHREADS     256
#define BONDED_TOTAL 13000                  // 2000 bond + 4000 angle + 6000 torsion + 1000 imptors

// ---------------------------------------------------------------------------
// Zero the Force region and E_ub
// ---------------------------------------------------------------------------
__global__ void zero_kernel(float* __restrict__ out) {
    int idx = blockIdx.x * blockDim.x + threadIdx.x;
    const int total = NS * (3 * N_ATOMS + 1);
    if (idx >= total) return;
    int s = idx / (3 * N_ATOMS + 1);
    int k = idx % (3 * N_ATOMS + 1);
    size_t base = (size_t)s * ROW;
    if (k < 3 * N_ATOMS)
        out[base + OFF_FORCE + k] = 0.0f;
    else
        out[base + OFF_EUB] = 0.0f;
}

// ---------------------------------------------------------------------------
// Fused everything kernel.
//   blocks [0, 400): vdw+charge, (chunk, sample), 2-replica smem force accum
//   blocks [400, 432): bonded terms (bond/angle/torsion/imptors), (sample, half)
// ---------------------------------------------------------------------------
__global__ __launch_bounds__(NTHREADS)
void fused_kernel(const float* __restrict__ length_bond,
                  const float* __restrict__ theta_angle,
                  const float* __restrict__ length_vdw,
                  const float* __restrict__ sin_cos_torsion,
                  const float* __restrict__ cos2_imptors,
                  const float* __restrict__ vdw14,
                  const float* __restrict__ charge14,
                  const float2* __restrict__ paras_bond,
                  const float2* __restrict__ paras_angle,
                  const float2* __restrict__ paras_vdw,
                  const float* __restrict__ paras_charge,
                  const float4* __restrict__ paras_torsion,
                  const float* __restrict__ paras_imptors,
                  const float* __restrict__ dlength_bond,
                  const float* __restrict__ dtheta_angle,
                  const float* __restrict__ dlength_vdw,
                  const float* __restrict__ dtheta_torsion,
                  const float* __restrict__ dcos2_imptors,
                  const int*   __restrict__ nonbonded,
                  const int2*  __restrict__ bond_index,
                  const int*   __restrict__ angle_index,
                  const int2*  __restrict__ nbindex,
                  const int4*  __restrict__ torsion_index,
                  const int4*  __restrict__ imptors_index,
                  float* __restrict__ out) {
    __shared__ float sF[2 * 3 * N_ATOMS];   // 48 KB; bonded path uses first half

    const int bx = blockIdx.x;

    if (bx < VDW_BLOCKS) {
        // ================= vdW + charge =================
        const int s     = bx / VDW_CHUNKS;
        const int chunk = bx % VDW_CHUNKS;
        const int c0    = chunk * VDW_CHUNK;

        for (int k = threadIdx.x; k < 2 * 3 * N_ATOMS; k += NTHREADS) sF[k] = 0.0f;
        __syncthreads();

        // replica split: warps 0-3 -> sFr[0..], warps 4-7 -> sFr[6000..]
        float* sFr = sF + ((threadIdx.x >> 7) & 1) * (3 * N_ATOMS);

        const float* Lrow = length_vdw + (size_t)s * NVV;
        const float* Drow = dlength_vdw + (size_t)s * NVV * 6;
        size_t base = (size_t)s * ROW;
        float* Ev = out + base + OFF_EVDW;
        float* Ec = out + base + OFF_ECHG;

        for (int p = c0 + threadIdx.x; p < c0 + VDW_CHUNK; p += NTHREADS) {
            int i = nonbonded[p];
            int j = nonbonded[NVV + p];
            float2 pvi = paras_vdw[i];
            float2 pvj = paras_vdw[j];
            float sigma = pvi.x + pvj.x;
            float eps   = (pvi.y * 0.1f) * (pvj.y * 0.1f) * vdw14[p];
            float cc    = (K2C_HALF * paras_charge[i]) * (K2C_HALF * paras_charge[j]) * charge14[p];

            float r   = Lrow[p];
            float ir  = __fdividef(1.0f, r);
            float ir2 = ir * ir;
            float s2  = sigma * sigma;
            float t   = (s2 * s2 * s2) * (ir2 * ir2 * ir2);

            Ev[p] = eps * (t * t - 2.0f * t);
            Ec[p] = cc * ir;

            float w = 12.0f * eps * t * (1.0f - t) * ir - cc * ir2;

            const float2* D = (const float2*)(Drow + (size_t)p * 6);
            float2 d0 = D[0], d1 = D[1], d2 = D[2];
            int2 ab = nbindex[p];
            atomicAdd(&sFr[ab.x * 3 + 0], d0.x * w);
            atomicAdd(&sFr[ab.x * 3 + 1], d0.y * w);
            atomicAdd(&sFr[ab.x * 3 + 2], d1.x * w);
            atomicAdd(&sFr[ab.y * 3 + 0], d1.y * w);
            atomicAdd(&sFr[ab.y * 3 + 1], d2.x * w);
            atomicAdd(&sFr[ab.y * 3 + 2], d2.y * w);
        }
        __syncthreads();

        float* F = out + base + OFF_FORCE;
        for (int k = threadIdx.x; k < 3 * N_ATOMS; k += NTHREADS) {
            float v = sF[k] + sF[3 * N_ATOMS + k];
            if (v != 0.0f) atomicAdd(&F[k], v);
        }
    } else {
        // ================= bonded terms =================
        const int bid  = bx - VDW_BLOCKS;
        const int s    = bid / BONDED_HALVES;
        const int half = bid % BONDED_HALVES;
        const int e0   = half * (BONDED_TOTAL / BONDED_HALVES);
        const int e1   = e0 + (BONDED_TOTAL / BONDED_HALVES);

        for (int k = threadIdx.x; k < 3 * N_ATOMS; k += NTHREADS) sF[k] = 0.0f;
        __syncthreads();

        size_t base = (size_t)s * ROW;

        for (int e = e0 + threadIdx.x; e < e1; e += NTHREADS) {
            if (e < 2000) {
                // ---- bond ----
                int b = e;
                float2 pb = paras_bond[b];
                float K = pb.x * 100.0f;
                float d = length_bond[(size_t)s * NB + b] - pb.y;
                out[base + OFF_EBOND + b] = K * d * d;
                float Fs = 2.0f * K * d;
                const float2* D = (const float2*)(dlength_bond + ((size_t)s * NB + b) * 6);
                float2 d0 = D[0], d1 = D[1], d2 = D[2];
                int2 ab = bond_index[b];
                atomicAdd(&sF[ab.x * 3 + 0], d0.x * Fs);
                atomicAdd(&sF[ab.x * 3 + 1], d0.y * Fs);
                atomicAdd(&sF[ab.x * 3 + 2], d1.x * Fs);
                atomicAdd(&sF[ab.y * 3 + 0], d1.y * Fs);
                atomicAdd(&sF[ab.y * 3 + 1], d2.x * Fs);
                atomicAdd(&sF[ab.y * 3 + 2], d2.y * Fs);
            } else if (e < 6000) {
                // ---- angle ----
                int a = e - 2000;
                float2 pa = paras_angle[a];
                float Ka  = pa.x * 10.0f;
                float th0 = pa.y * 0.3141592653589793f;
                float da  = theta_angle[(size_t)s * NA + a] - th0;
                out[base + OFF_EANGLE + a] = Ka * da * da;
                float Fs = 2.0f * Ka * da;
                const float* D = dtheta_angle + ((size_t)s * NA + a) * 9;
                #pragma unroll
                for (int k = 0; k < 3; k++) {
                    int atom = angle_index[a * 3 + k];
                    #pragma unroll
                    for (int c = 0; c < 3; c++)
                        atomicAdd(&sF[atom * 3 + c], D[k * 3 + c] * Fs);
                }
            } else if (e < 12000) {
                // ---- torsion ----
                int t = e - 6000;
                const float4* SC = (const float4*)(sin_cos_torsion + ((size_t)s * NT + t) * 8);
                float4 sc0 = SC[0];   // sin1, cos1, sin2, cos2
                float4 sc1 = SC[1];   // sin3, cos3, sin4, cos4
                float4 p = paras_torsion[t];
                float E = sc0.y * p.x + sc0.w * p.y + sc1.y * p.z + sc1.w * p.w;
                out[base + OFF_ETOR + t] = E;
                float Fs = -(sc0.x * p.x + sc0.z * (2.0f * p.y) +
                             sc1.x * (3.0f * p.z) + sc1.z * (4.0f * p.w));
                const float4* D = (const float4*)(dtheta_torsion + ((size_t)s * NT + t) * 12);
                float4 dA = D[0], dB = D[1], dC = D[2];
                int4 ti = torsion_index[t];
                atomicAdd(&sF[ti.x * 3 + 0], dA.x * Fs);
                atomicAdd(&sF[ti.x * 3 + 1], dA.y * Fs);
                atomicAdd(&sF[ti.x * 3 + 2], dA.z * Fs);
                atomicAdd(&sF[ti.y * 3 + 0], dA.w * Fs);
                atomicAdd(&sF[ti.y * 3 + 1], dB.x * Fs);
                atomicAdd(&sF[ti.y * 3 + 2], dB.y * Fs);
                atomicAdd(&sF[ti.z * 3 + 0], dB.z * Fs);
                atomicAdd(&sF[ti.z * 3 + 1], dB.w * Fs);
                atomicAdd(&sF[ti.z * 3 + 2], dC.x * Fs);
                atomicAdd(&sF[ti.w * 3 + 0], dC.y * Fs);
                atomicAdd(&sF[ti.w * 3 + 1], dC.z * Fs);
                atomicAdd(&sF[ti.w * 3 + 2], dC.w * Fs);
            } else {
                // ---- imptors ----
                int i = e - 12000;
                float ki = paras_imptors[i];
                out[base + OFF_EIMP + i] = ki * (1.0f - cos2_imptors[(size_t)s * NI + i]);
                float Fs = -ki;
                const float4* D = (const float4*)(dcos2_imptors + ((size_t)s * NI + i) * 12);
                float4 dA = D[0], dB = D[1], dC = D[2];
                int4 ii = imptors_index[i];
                atomicAdd(&sF[ii.x * 3 + 0], dA.x * Fs);
                atomicAdd(&sF[ii.x * 3 + 1], dA.y * Fs);
                atomicAdd(&sF[ii.x * 3 + 2], dA.z * Fs);
                atomicAdd(&sF[ii.y * 3 + 0], dA.w * Fs);
                atomicAdd(&sF[ii.y * 3 + 1], dB.x * Fs);
                atomicAdd(&sF[ii.y * 3 + 2], dB.y * Fs);
                atomicAdd(&sF[ii.z * 3 + 0], dB.z * Fs);
                atomicAdd(&sF[ii.z * 3 + 1], dB.w * Fs);
                atomicAdd(&sF[ii.z * 3 + 2], dC.x * Fs);
                atomicAdd(&sF[ii.w * 3 + 0], dC.y * Fs);
                atomicAdd(&sF[ii.w * 3 + 1], dC.z * Fs);
                atomicAdd(&sF[ii.w * 3 + 2], dC.w * Fs);
            }
        }
        __syncthreads();

        float* F = out + base + OFF_FORCE;
        for (int k = threadIdx.x; k < 3 * N_ATOMS; k += NTHREADS) {
            float v = sF[k];
            if (v != 0.0f) atomicAdd(&F[k], v);
        }
    }
}

// ---------------------------------------------------------------------------
// Launch
// ---------------------------------------------------------------------------
extern "C" void kernel_launch(void* const* d_in, const int* in_sizes, int n_in,
                              void* d_out, int out_size) {
    const float* length_bond     = (const float*)d_in[0];
    const float* theta_angle     = (const float*)d_in[1];
    const float* length_vdw      = (const float*)d_in[2];
    const float* sin_cos_torsion = (const float*)d_in[3];
    const float* cos2_imptors    = (const float*)d_in[4];
    const float* vdw14           = (const float*)d_in[5];
    const float* charge14        = (const float*)d_in[6];
    const float* paras_bond      = (const float*)d_in[7];
    const float* paras_angle     = (const float*)d_in[8];
    const float* paras_vdw       = (const float*)d_in[9];
    const float* paras_charge    = (const float*)d_in[10];
    const float* paras_torsion   = (const float*)d_in[11];
    const float* paras_imptors   = (const float*)d_in[12];
    const float* dlength_bond    = (const float*)d_in[13];
    const float* dtheta_angle    = (const float*)d_in[14];
    const float* dlength_vdw     = (const float*)d_in[15];
    const float* dtheta_torsion  = (const float*)d_in[16];
    const float* dcos2_imptors   = (const float*)d_in[17];
    const int*   nonbonded       = (const int*)d_in[18];
    const int*   bond_index      = (const int*)d_in[19];
    const int*   angle_index     = (const int*)d_in[20];
    const int*   nonbonded_index = (const int*)d_in[21];
    const int*   torsion_index   = (const int*)d_in[22];
    const int*   imptors_index   = (const int*)d_in[23];
    float* out = (float*)d_out;

    {
        int total = NS * (3 * N_ATOMS + 1);
        zero_kernel<<<(total + 255) / 256, 256>>>(out);
    }
    fused_kernel<<<TOTAL_BLOCKS, NTHREADS>>>(
        length_bond, theta_angle, length_vdw, sin_cos_torsion, cos2_imptors,
        vdw14, charge14,
        (const float2*)paras_bond, (const float2*)paras_angle,
        (const float2*)paras_vdw, paras_charge,
        (const float4*)paras_torsion, paras_imptors,
        dlength_bond, dtheta_angle, dlength_vdw, dtheta_torsion, dcos2_imptors,
        nonbonded, (const int2*)bond_index, angle_index,
        (const int2*)nonbonded_index, (const int4*)torsion_index,
        (const int4*)imptors_index, out);
}